// round 3
// baseline (speedup 1.0000x reference)
#include <cuda_runtime.h>

// Residual VQ (L=8, G=2, K=1024, D=256), B=16, T=4096, N=B*T=65536.
// Bit-replicates CPU-JAX (XLA/Eigen) fp32 semantics of the reference:
//   a_n  = sequential d-ascending sum of fl(x_d^2)          (separate mul/add rounding)
//   b_k  = sequential d-ascending sum of fl(e_d^2)
//   c_nk = sequential d-ascending fused-FMA dot (Eigen gebp)
//   d    = fl( fl(a + b_k) - 2*c_nk ),  argmin first-index
//   delta= fl(zq - x); quant = fl(x + delta); r' = fl(x - quant)
// Outputs (fp32, concatenated reference return order, guarded by out_size):
//   [0, 33554432) quantized_out [B,C,T]; [33554432] loss; [33554433,+1048576) indices [L,G,N]

#define LL 8
#define GG 2
#define KK 1024
#define DD 256
#define TT 4096
#define NTOK 65536ull
#define TILE 64
#define NTH 256
#define EPITCH 132

#define QOUT_ELEMS 33554432ull
#define LOSS_OFF   33554432ull
#define IDX_OFF    33554433ull

__device__ float  g_e2[LL * GG * KK];
__device__ double g_loss[2048];

// ---------------------------------------------------------------- ||e||^2 (exact ref rounding)
__global__ void e2_kernel(const float* __restrict__ cb) {
    int c = blockIdx.x * blockDim.x + threadIdx.x;   // 0 .. 16383
    if (c >= LL * GG * KK) return;
    const float* e = cb + (size_t)c * DD;
    float s = 0.0f;
    for (int d = 0; d < DD; ++d) {
        float v = e[d];
        s = __fadd_rn(s, __fmul_rn(v, v));           // square rounded, then add rounded
    }
    g_e2[c] = s;
}

// ---------------------------------------------------------------- main
__global__ void __launch_bounds__(NTH, 2)
rvq_kernel(const float* __restrict__ xin, const float* __restrict__ cb,
           float* __restrict__ dout, unsigned long long out_size) {
    extern __shared__ float sm[];
    float* X    = sm;                         // [256][64] residual, [d][t]
    float* E    = X + DD * TILE;              // [16][EPITCH] transposed e chunk
    float* E2s  = E + 16 * EPITCH;            // [128] ||e||^2 of current code block
    float* SCRV = E2s + 128;                  // [64][16]
    int*   SCRI = (int*)(SCRV + TILE * 16);   // [64][16]
    float* RUNV = (float*)(SCRI + TILE * 16); // [64]
    int*   RUNI = (int*)(RUNV + TILE);        // [64]
    float* Asm  = (float*)(RUNI + TILE);      // [64] ||x||^2 per token

    const int tid  = threadIdx.x;
    const int g    = blockIdx.y;
    const int tile = blockIdx.x;
    const int b    = tile >> 6;
    const int t0   = (tile & 63) << 6;
    const float* xb = xin + ((size_t)b * (GG * DD) + (size_t)g * DD) * TT + t0;

    // residual := xin tile, [d][t] layout (coalesced over t)
    for (int i = tid; i < DD * TILE; i += NTH) {
        int d = i >> 6, t = i & 63;
        X[i] = xb[(size_t)d * TT + t];
    }
    __syncthreads();

    const int tm = tid & 15;   // token group: tokens 4*tm .. 4*tm+3
    const int tn = tid >> 4;   // code group:  codes  8*tn .. 8*tn+7
    const int q  = tid & 3;    // d-quad for chunk loads
    const int kc = tid >> 2;   // code row for chunk loads (0..63)

    double lacc = 0.0;

    for (int l = 0; l < LL; ++l) {
        const float* cbl = cb + ((size_t)(l * GG + g)) * KK * DD;

        // a_n = sequential sum of fl(x^2), d ascending (XLA scalar reduce order)
        if (tid < TILE) {
            float s = 0.0f;
            const float* xc = X + tid;
#pragma unroll 8
            for (int d = 0; d < DD; ++d) {
                float v = xc[d * TILE];
                s = __fadd_rn(s, __fmul_rn(v, v));
            }
            Asm[tid] = s;
            RUNV[tid] = 3.0e38f; RUNI[tid] = 0;
        }
        __syncthreads();

        for (int kb = 0; kb < 8; ++kb) {               // 8 blocks of 128 codes
            const float* cblk = cbl + (size_t)kb * 128 * DD;
            if (tid < 128) E2s[tid] = g_e2[(l * GG + g) * KK + kb * 128 + tid];

            float acc[4][8];
#pragma unroll
            for (int i = 0; i < 4; ++i)
#pragma unroll
                for (int j = 0; j < 8; ++j) acc[i][j] = 0.f;

#pragma unroll 1
            for (int dc = 0; dc < 16; ++dc) {          // 16 d-chunks of 16
                __syncthreads();                        // E readers done
#pragma unroll
                for (int p = 0; p < 2; ++p) {          // load+transpose 128 codes x 16 d
                    int code = p * 64 + kc;
                    float4 v = *(const float4*)(cblk + (size_t)code * DD + dc * 16 + q * 4);
                    E[(q * 4 + 0) * EPITCH + code] = v.x;
                    E[(q * 4 + 1) * EPITCH + code] = v.y;
                    E[(q * 4 + 2) * EPITCH + code] = v.z;
                    E[(q * 4 + 3) * EPITCH + code] = v.w;
                }
                __syncthreads();
#pragma unroll
                for (int dd = 0; dd < 16; ++dd) {      // sequential d ascending, fused FMA
                    const float* xr = X + (dc * 16 + dd) * TILE + 4 * tm;
                    float4 a  = *(const float4*)xr;
                    float4 b0 = *(const float4*)(E + dd * EPITCH + 8 * tn);
                    float4 b1 = *(const float4*)(E + dd * EPITCH + 8 * tn + 4);
                    float av[4] = {a.x, a.y, a.z, a.w};
                    float bv[8] = {b0.x, b0.y, b0.z, b0.w, b1.x, b1.y, b1.z, b1.w};
#pragma unroll
                    for (int i = 0; i < 4; ++i)
#pragma unroll
                        for (int j = 0; j < 8; ++j)
                            acc[i][j] = fmaf(av[i], bv[j], acc[i][j]);
                }
            }

            // local argmin with exact reference rounding:
            // d = fl( fl(a + b_k) - 2c )   (2c exact)
#pragma unroll
            for (int i = 0; i < 4; ++i) {
                float a_tok = Asm[4 * tm + i];
                float best = 3.0e38f; int bi = 0;
#pragma unroll
                for (int j = 0; j < 8; ++j) {
                    float t1 = __fadd_rn(a_tok, E2s[8 * tn + j]);
                    float dv = __fadd_rn(t1, __fmul_rn(-2.0f, acc[i][j]));
                    if (dv < best) { best = dv; bi = j; }
                }
                SCRV[(4 * tm + i) * 16 + tn] = best;
                SCRI[(4 * tm + i) * 16 + tn] = kb * 128 + 8 * tn + bi;
            }
            __syncthreads();
            if (tid < TILE) {                           // merge, first-index wins
                float bv = RUNV[tid]; int bi = RUNI[tid];
#pragma unroll
                for (int t16 = 0; t16 < 16; ++t16) {
                    float v = SCRV[tid * 16 + t16];
                    if (v < bv) { bv = v; bi = SCRI[tid * 16 + t16]; }
                }
                RUNV[tid] = bv; RUNI[tid] = bi;
            }
            __syncthreads();
        }

        // indices out
        if (tid < TILE && out_size > IDX_OFF) {
            size_t n = (size_t)b * TT + t0 + tid;
            size_t o = IDX_OFF + ((size_t)(l * GG + g)) * NTOK + n;
            if (o < out_size) dout[o] = (float)RUNI[tid];
        }

        // residual update, elementwise-identical to reference STE:
        //   delta = fl(zq - x); quant = fl(x + delta); x' = fl(x - quant)
        {
            int token = tid >> 2, dq = tid & 3;
            int code  = RUNI[token];
            const float* ev = cbl + (size_t)code * DD + dq * 64;
            float* xc = X + (dq * 64) * TILE + token;
#pragma unroll 8
            for (int dd = 0; dd < 64; ++dd) {
                float x  = xc[dd * TILE];
                float dl = __fsub_rn(ev[dd], x);
                float qn = __fadd_rn(x, dl);
                xc[dd * TILE] = __fsub_rn(x, qn);
                lacc += (double)dl * (double)dl;
            }
        }
        __syncthreads();
    }

    // quantized_out = xin - final residual (differs from sum-of-quant by ~1e-7/elem, OK)
    for (int i = tid; i < DD * TILE; i += NTH) {
        int d = i >> 6, t = i & 63;
        size_t o = ((size_t)b * (GG * DD) + (size_t)g * DD + d) * TT + t0 + t;
        if (o < out_size && o < QOUT_ELEMS)
            dout[o] = __fsub_rn(xb[(size_t)d * TT + t], X[i]);
    }

    // deterministic per-CTA loss partial
    double* red = (double*)SCRV;
    red[tid] = lacc;
    __syncthreads();
    for (int s = 128; s > 0; s >>= 1) {
        if (tid < s) red[tid] += red[tid + s];
        __syncthreads();
    }
    if (tid == 0) g_loss[blockIdx.y * 1024 + blockIdx.x] = red[0];
}

// ---------------------------------------------------------------- loss reduce
__global__ void loss_kernel(float* __restrict__ dout, unsigned long long out_size) {
    __shared__ double red[256];
    int tid = threadIdx.x;
    double s = 0.0;
    for (int i = tid; i < 2048; i += 256) s += g_loss[i];   // fixed order
    red[tid] = s;
    __syncthreads();
    for (int st = 128; st > 0; st >>= 1) {
        if (tid < st) red[tid] += red[tid + st];
        __syncthreads();
    }
    if (tid == 0 && out_size > LOSS_OFF)
        dout[LOSS_OFF] = (float)(1.25 * red[0] / (8.0 * 33554432.0));
}

// ---------------------------------------------------------------- launch
extern "C" void kernel_launch(void* const* d_in, const int* in_sizes, int n_in,
                              void* d_out, int out_size) {
    const float* xin = (const float*)d_in[0];
    const float* cb  = (const float*)d_in[1];
    if (n_in >= 2 && in_sizes[0] == LL * GG * KK * DD) {  // defensive order swap
        xin = (const float*)d_in[1];
        cb  = (const float*)d_in[0];
    }
    float* dout = (float*)d_out;
    unsigned long long osz = (unsigned long long)out_size;

    static bool attr_set = false;
    size_t smem = (size_t)(DD * TILE + 16 * EPITCH + 128 + TILE * 16 * 2 + TILE * 2 + TILE) * 4;
    if (!attr_set) {
        cudaFuncSetAttribute(rvq_kernel, cudaFuncAttributeMaxDynamicSharedMemorySize, (int)smem);
        attr_set = true;
    }

    e2_kernel<<<(LL * GG * KK + 255) / 256, 256>>>(cb);
    dim3 grid(1024, GG);
    rvq_kernel<<<grid, NTH, smem>>>(xin, cb, dout, osz);
    loss_kernel<<<1, 256>>>(dout, osz);
}